// round 13
// baseline (speedup 1.0000x reference)
#include <cuda_runtime.h>
#include <cuda_fp16.h>
#include <cstdint>

#define NUM_EMB 41025
#define BATCH   16384
#define BAG     30
#define BAGP    32
#define P       8          // positions per block (1 warp each)
#define NT      256
#define GRID    (BATCH / P)

#define ROW_U4   32                    // 256 halves = 32 uint4 per row
#define ROW_B    512                   // bytes per row
#define TBL_U4   (NUM_EMB * ROW_U4)

#define NSTAGE   3
#define CHUNKS   8                     // 8 chunks x 4 rows = 32 rows (padded)
#define CHUNK_B  (8 * ROW_B)           // 2 tables x 4 rows = 4096 B per chunk

// dynamic smem layout (bytes)
#define OFF_ROWS 0
#define SZ_ROWS  (P * NSTAGE * CHUNK_B)          // 8*3*4096 = 98304
#define OFF_IDX  (OFF_ROWS + SZ_ROWS)            // 98304
#define SZ_IDX   (P * 2 * BAGP * 4)              // 2048
#define OFF_XH   (OFF_IDX + SZ_IDX)              // 100352
#define SZ_XH    (P * 256 * 4)                   // 8192 (half2)
#define OFF_H1   (OFF_XH + SZ_XH)                // 108544
#define SZ_H1    (P * 32 * 4)                    // 1024
#define OFF_MBAR (OFF_H1 + SZ_H1)                // 109568
#define SZ_MBAR  (P * NSTAGE * 8)                // 192
#define SMEM_TOTAL (OFF_MBAR + SZ_MBAR)          // 109760

// fp16 shadow tables (scratch): [0]=white, [1]=black. 21 MB each.
__device__ uint4 g_ft16[2][TBL_U4];

// ---- packed f32x2 helpers ----
__device__ __forceinline__ void add_f32x2(uint64_t& acc, uint64_t v) {
    asm("add.rn.f32x2 %0, %1, %2;" : "=l"(acc) : "l"(acc), "l"(v));
}
__device__ __forceinline__ void fma_f32x2(uint64_t& acc, uint64_t a, uint64_t b) {
    asm("fma.rn.f32x2 %0, %1, %2, %3;" : "=l"(acc) : "l"(a), "l"(b), "l"(acc));
}
__device__ __forceinline__ uint64_t h2_to_f32x2(__half2 h) {
    float2 f = __half22float2(h);
    uint64_t r;
    asm("mov.b64 %0, {%1, %2};" : "=l"(r) : "f"(f.x), "f"(f.y));
    return r;
}
__device__ __forceinline__ float2 unpack_f32x2(uint64_t v) {
    float2 f;
    asm("mov.b64 {%0, %1}, %2;" : "=f"(f.x), "=f"(f.y) : "l"(v));
    return f;
}
__device__ __forceinline__ uint64_t pack_f32x2(float x, float y) {
    uint64_t r;
    asm("mov.b64 %0, {%1, %2};" : "=l"(r) : "f"(x), "f"(y));
    return r;
}

// ---- mbarrier / bulk-copy helpers ----
__device__ __forceinline__ void mbar_init(uint32_t addr, uint32_t count) {
    asm volatile("mbarrier.init.shared.b64 [%0], %1;" :: "r"(addr), "r"(count) : "memory");
}
__device__ __forceinline__ void mbar_expect_tx(uint32_t addr, uint32_t bytes) {
    asm volatile("mbarrier.arrive.expect_tx.shared.b64 _, [%0], %1;"
                 :: "r"(addr), "r"(bytes) : "memory");
}
__device__ __forceinline__ void mbar_wait(uint32_t addr, uint32_t phase) {
    asm volatile(
        "{\n\t.reg .pred P;\n"
        "W%=:\n\t"
        "mbarrier.try_wait.parity.acquire.cta.shared::cta.b64 P, [%0], %1;\n\t"
        "@P bra D%=;\n\t"
        "bra W%=;\n"
        "D%=:\n\t}"
        :: "r"(addr), "r"(phase) : "memory");
}
__device__ __forceinline__ void bulk_copy_g2s(uint32_t dst, const void* src,
                                              uint32_t bytes, uint32_t mbar) {
    asm volatile(
        "cp.async.bulk.shared::cluster.global.mbarrier::complete_tx::bytes "
        "[%0], [%1], %2, [%3];"
        :: "r"(dst), "l"(src), "r"(bytes), "r"(mbar) : "memory");
}

// ---------------------------------------------------------------------------
// Pre-pass: convert both f32 tables to fp16 (streaming reads, L2 writes).
// ---------------------------------------------------------------------------
__global__ __launch_bounds__(256)
void cvt_kernel(const float4* __restrict__ ftw, const float4* __restrict__ ftb)
{
    const int i = blockIdx.x * blockDim.x + threadIdx.x;
    if (i >= 2 * TBL_U4) return;
    const int tbl = (i >= TBL_U4);
    const int j   = tbl ? (i - TBL_U4) : i;
    const float4* src = tbl ? ftb : ftw;

    const float4 a = __ldcs(&src[2 * j]);
    const float4 b = __ldcs(&src[2 * j + 1]);

    __half2 h0 = __floats2half2_rn(a.x, a.y);
    __half2 h1 = __floats2half2_rn(a.z, a.w);
    __half2 h2 = __floats2half2_rn(b.x, b.y);
    __half2 h3 = __floats2half2_rn(b.z, b.w);

    uint4 o;
    o.x = *reinterpret_cast<unsigned*>(&h0);
    o.y = *reinterpret_cast<unsigned*>(&h1);
    o.z = *reinterpret_cast<unsigned*>(&h2);
    o.w = *reinterpret_cast<unsigned*>(&h3);
    __stcg(&g_ft16[tbl][j], o);
}

// ---------------------------------------------------------------------------
// Main kernel: TMA bulk-copy gather pipeline (per-warp, 3-stage).
// ---------------------------------------------------------------------------
__global__ __launch_bounds__(NT, 2)
void nnue_kernel(const int* __restrict__ wi,
                 const int* __restrict__ bi,
                 const float4* __restrict__ fc1w,   // [32][128] float4
                 const float* __restrict__ fc1b,
                 const float4* __restrict__ fc2w,   // [32][8] float4
                 const float* __restrict__ fc2b,
                 const float* __restrict__ fc3w,
                 const float* __restrict__ fc3b,
                 float* __restrict__ out)
{
    extern __shared__ __align__(1024) char dsm[];
    int*     s_idx = reinterpret_cast<int*>(dsm + OFF_IDX);      // [P][2][BAGP]
    __half2* s_xh  = reinterpret_cast<__half2*>(dsm + OFF_XH);   // [P][256]
    float*   s_h1  = reinterpret_cast<float*>(dsm + OFF_H1);     // [P][32]

    const int tid  = threadIdx.x;
    const int lane = tid & 31;
    const int warp = tid >> 5;
    const int p0   = blockIdx.x * P;

    const uint32_t smem_u32 = (uint32_t)__cvta_generic_to_shared(dsm);
    const uint32_t rows_w   = smem_u32 + OFF_ROWS + warp * (NSTAGE * CHUNK_B);
    const uint32_t mbar_w   = smem_u32 + OFF_MBAR + warp * (NSTAGE * 8);

    // ---- mbarrier init (per-warp) ----
    if (lane == 0) {
#pragma unroll
        for (int s = 0; s < NSTAGE; s++)
            mbar_init(mbar_w + 8 * s, 1);
        asm volatile("fence.proxy.async.shared::cta;" ::: "memory");
    }

    // ---- stage indices (padded to 32; pad index 0 -> all-zero table row) ----
    for (int i = tid; i < P * 2 * BAGP; i += NT) {
        const int pp  = i / (2 * BAGP);
        const int r   = i % (2 * BAGP);
        const int tbl = r / BAGP;
        const int j   = r % BAGP;
        int v = 0;
        if (j < BAG)
            v = tbl ? bi[(p0 + pp) * BAG + j] : wi[(p0 + pp) * BAG + j];
        s_idx[(pp * 2 + tbl) * BAGP + j] = v;
    }
    __syncthreads();

    // ---- gather via cp.async.bulk: warp w owns position w ----
    {
        const int* idx_w = s_idx + warp * 2 * BAGP;   // [2][BAGP]

        // issue helper (lambda-ish via macro-free code): chunk cc -> buf cc%NSTAGE
        auto issue = [&](int cc) {
            const uint32_t mb  = mbar_w + 8 * (cc % NSTAGE);
            if (lane == 0)
                mbar_expect_tx(mb, CHUNK_B);
            __syncwarp();
            if (lane < 8) {
                const int tbl = lane >> 2;
                const int row = lane & 3;
                const int idx = idx_w[tbl * BAGP + 4 * cc + row];
                const char* src = reinterpret_cast<const char*>(g_ft16[tbl])
                                  + (size_t)idx * ROW_B;
                const uint32_t dst = rows_w + (cc % NSTAGE) * CHUNK_B
                                     + lane * ROW_B;
                bulk_copy_g2s(dst, src, ROW_B, mb);
            }
        };

        issue(0); issue(1); issue(2);

        uint64_t accW[4], accB[4];
#pragma unroll
        for (int k = 0; k < 4; k++) { accW[k] = 0ull; accB[k] = 0ull; }

#pragma unroll
        for (int c = 0; c < CHUNKS; c++) {
            mbar_wait(mbar_w + 8 * (c % NSTAGE), (c / NSTAGE) & 1);

            const char* buf = dsm + OFF_ROWS + warp * (NSTAGE * CHUNK_B)
                              + (c % NSTAGE) * CHUNK_B;
            const uint4 vw0 = *reinterpret_cast<const uint4*>(buf + 0 * ROW_B + lane * 16);
            const uint4 vw1 = *reinterpret_cast<const uint4*>(buf + 1 * ROW_B + lane * 16);
            const uint4 vw2 = *reinterpret_cast<const uint4*>(buf + 2 * ROW_B + lane * 16);
            const uint4 vw3 = *reinterpret_cast<const uint4*>(buf + 3 * ROW_B + lane * 16);
            const uint4 vb0 = *reinterpret_cast<const uint4*>(buf + 4 * ROW_B + lane * 16);
            const uint4 vb1 = *reinterpret_cast<const uint4*>(buf + 5 * ROW_B + lane * 16);
            const uint4 vb2 = *reinterpret_cast<const uint4*>(buf + 6 * ROW_B + lane * 16);
            const uint4 vb3 = *reinterpret_cast<const uint4*>(buf + 7 * ROW_B + lane * 16);

            const __half2* w0 = reinterpret_cast<const __half2*>(&vw0);
            const __half2* w1 = reinterpret_cast<const __half2*>(&vw1);
            const __half2* w2 = reinterpret_cast<const __half2*>(&vw2);
            const __half2* w3 = reinterpret_cast<const __half2*>(&vw3);
            const __half2* b0 = reinterpret_cast<const __half2*>(&vb0);
            const __half2* b1 = reinterpret_cast<const __half2*>(&vb1);
            const __half2* b2 = reinterpret_cast<const __half2*>(&vb2);
            const __half2* b3 = reinterpret_cast<const __half2*>(&vb3);

#pragma unroll
            for (int k = 0; k < 4; k++) {
                __half2 hw = __hadd2(__hadd2(w0[k], w1[k]),
                                     __hadd2(w2[k], w3[k]));
                __half2 hb = __hadd2(__hadd2(b0[k], b1[k]),
                                     __hadd2(b2[k], b3[k]));
                add_f32x2(accW[k], h2_to_f32x2(hw));
                add_f32x2(accB[k], h2_to_f32x2(hb));
            }

            if (c + NSTAGE < CHUNKS)
                issue(c + NSTAGE);
        }

        // relu in f32, convert to fp16, store x to smem (2 x STS.128 / warp).
        __half2 hW[4], hB[4];
#pragma unroll
        for (int k = 0; k < 4; k++) {
            float2 fw = unpack_f32x2(accW[k]);
            float2 fb = unpack_f32x2(accB[k]);
            hW[k] = __floats2half2_rn(fmaxf(fw.x, 0.f), fmaxf(fw.y, 0.f));
            hB[k] = __floats2half2_rn(fmaxf(fb.x, 0.f), fmaxf(fb.y, 0.f));
        }
        *reinterpret_cast<uint4*>(&s_xh[warp * 256 + 4 * lane]) =
            *reinterpret_cast<uint4*>(hW);
        *reinterpret_cast<uint4*>(&s_xh[warp * 256 + 128 + 4 * lane]) =
            *reinterpret_cast<uint4*>(hB);
    }

    // ---- FC1 weights -> 64 registers (once per block) ----
    uint64_t wp[4][8];
    float    b1r[4];
#pragma unroll
    for (int oo = 0; oo < 4; oo++) {
        const int o = 4 * warp + oo;
#pragma unroll
        for (int k = 0; k < 4; k++) {
            const float4 w = __ldg(&fc1w[(size_t)o * 128 + lane + 32 * k]);
            wp[oo][2 * k]     = pack_f32x2(w.x, w.y);
            wp[oo][2 * k + 1] = pack_f32x2(w.z, w.w);
        }
        b1r[oo] = __ldg(&fc1b[o]);
    }
    __syncthreads();

    // ---- FC1: warp computes its 4 outputs for all 8 positions ----
#pragma unroll
    for (int pos = 0; pos < P; pos++) {
        uint64_t xp[8];
#pragma unroll
        for (int k = 0; k < 4; k++) {
            const uint2 v = *reinterpret_cast<const uint2*>(
                &s_xh[pos * 256 + 2 * (lane + 32 * k)]);
            const __half2 lo = *reinterpret_cast<const __half2*>(&v.x);
            const __half2 hi = *reinterpret_cast<const __half2*>(&v.y);
            xp[2 * k]     = h2_to_f32x2(lo);
            xp[2 * k + 1] = h2_to_f32x2(hi);
        }
        float part[4];
#pragma unroll
        for (int oo = 0; oo < 4; oo++) {
            uint64_t acc = 0ull;
#pragma unroll
            for (int k = 0; k < 8; k++)
                fma_f32x2(acc, wp[oo][k], xp[k]);
            const float2 f = unpack_f32x2(acc);
            part[oo] = f.x + f.y;
        }
#pragma unroll
        for (int off = 16; off > 0; off >>= 1) {
#pragma unroll
            for (int oo = 0; oo < 4; oo++)
                part[oo] += __shfl_xor_sync(0xffffffffu, part[oo], off);
        }
        if (lane == 0) {
#pragma unroll
            for (int oo = 0; oo < 4; oo++)
                s_h1[pos * 32 + 4 * warp + oo] = fmaxf(part[oo] + b1r[oo], 0.f);
        }
    }
    __syncthreads();

    // ---- FC2 (32->32, relu) + FC3 (32->1): warp w handles position w ----
    {
        const float* h = s_h1 + warp * 32;
        float s = __ldg(&fc2b[lane]);
        const float4* w2 = fc2w + (size_t)lane * 8;
#pragma unroll
        for (int k = 0; k < 8; k++) {
            const float4 w = __ldg(&w2[k]);
            s += w.x * h[4 * k + 0];
            s += w.y * h[4 * k + 1];
            s += w.z * h[4 * k + 2];
            s += w.w * h[4 * k + 3];
        }
        float v = fmaxf(s, 0.f) * __ldg(&fc3w[lane]);
#pragma unroll
        for (int off = 16; off > 0; off >>= 1)
            v += __shfl_xor_sync(0xffffffffu, v, off);
        if (lane == 0)
            out[p0 + warp] = v + __ldg(&fc3b[0]);
    }
}

extern "C" void kernel_launch(void* const* d_in, const int* in_sizes, int n_in,
                              void* d_out, int out_size)
{
    const int*    wiP   = (const int*)d_in[0];
    const int*    biP   = (const int*)d_in[2];
    const float4* ftw   = (const float4*)d_in[4];
    const float4* ftb   = (const float4*)d_in[5];
    const float4* fc1w  = (const float4*)d_in[6];
    const float*  fc1b  = (const float*)d_in[7];
    const float4* fc2w  = (const float4*)d_in[8];
    const float*  fc2b  = (const float*)d_in[9];
    const float*  fc3w  = (const float*)d_in[10];
    const float*  fc3b  = (const float*)d_in[11];
    float* outP = (float*)d_out;

    static bool attr_done = false;
    if (!attr_done) {
        cudaFuncSetAttribute(nnue_kernel,
                             cudaFuncAttributeMaxDynamicSharedMemorySize,
                             SMEM_TOTAL);
        attr_done = true;
    }

    const int n_cvt = 2 * TBL_U4;
    cvt_kernel<<<(n_cvt + 255) / 256, 256>>>(ftw, ftb);
    nnue_kernel<<<GRID, NT, SMEM_TOTAL>>>(wiP, biP, fc1w, fc1b,
                                          fc2w, fc2b, fc3w, fc3b, outP);
}

// round 14
// speedup vs baseline: 1.1436x; 1.1436x over previous
#include <cuda_runtime.h>
#include <cuda_fp16.h>
#include <cstdint>

#define NUM_EMB 41025
#define BATCH   16384
#define BAG     30
#define BAGP    32         // padded bag (pad index = 0 -> zero row)
#define P       8          // positions per block
#define NT      256
#define GRID    (BATCH / P)

#define ROW_U4  32                     // 256 halves = 32 uint4 per row
#define TBL_U4  (NUM_EMB * ROW_U4)     // 1,312,800 uint4 per table

// fp16 shadow tables (scratch): [0]=white, [1]=black. 21 MB each.
__device__ uint4 g_ft16[2][TBL_U4];

// ---- packed f32x2 helpers (Blackwell sm_103a) ----
__device__ __forceinline__ void add_f32x2(uint64_t& acc, uint64_t v) {
    asm("add.rn.f32x2 %0, %1, %2;" : "=l"(acc) : "l"(acc), "l"(v));
}
__device__ __forceinline__ void fma_f32x2(uint64_t& acc, uint64_t a, uint64_t b) {
    asm("fma.rn.f32x2 %0, %1, %2, %3;" : "=l"(acc) : "l"(a), "l"(b), "l"(acc));
}
__device__ __forceinline__ uint64_t h2_to_f32x2(__half2 h) {
    float2 f = __half22float2(h);
    uint64_t r;
    asm("mov.b64 %0, {%1, %2};" : "=l"(r) : "f"(f.x), "f"(f.y));
    return r;
}
__device__ __forceinline__ float2 unpack_f32x2(uint64_t v) {
    float2 f;
    asm("mov.b64 {%0, %1}, %2;" : "=f"(f.x), "=f"(f.y) : "l"(v));
    return f;
}
__device__ __forceinline__ uint64_t pack_f32x2(float x, float y) {
    uint64_t r;
    asm("mov.b64 %0, {%1, %2};" : "=l"(r) : "f"(x), "f"(y));
    return r;
}

// ---------------------------------------------------------------------------
// Pre-pass: convert both f32 tables to fp16 (streaming reads, L2 writes).
// Signals PDL dependents as soon as this block's stores are issued.
// ---------------------------------------------------------------------------
__global__ __launch_bounds__(256)
void cvt_kernel(const float4* __restrict__ ftw, const float4* __restrict__ ftb)
{
    const int i = blockIdx.x * blockDim.x + threadIdx.x;
    if (i < 2 * TBL_U4) {
        const int tbl = (i >= TBL_U4);
        const int j   = tbl ? (i - TBL_U4) : i;
        const float4* src = tbl ? ftb : ftw;

        const float4 a = __ldcs(&src[2 * j]);
        const float4 b = __ldcs(&src[2 * j + 1]);

        __half2 h0 = __floats2half2_rn(a.x, a.y);
        __half2 h1 = __floats2half2_rn(a.z, a.w);
        __half2 h2 = __floats2half2_rn(b.x, b.y);
        __half2 h3 = __floats2half2_rn(b.z, b.w);

        uint4 o;
        o.x = *reinterpret_cast<unsigned*>(&h0);
        o.y = *reinterpret_cast<unsigned*>(&h1);
        o.z = *reinterpret_cast<unsigned*>(&h2);
        o.w = *reinterpret_cast<unsigned*>(&h3);
        __stcg(&g_ft16[tbl][j], o);
    }
    // Allow dependent (main) grid blocks to begin scheduling.
    asm volatile("griddepcontrol.launch_dependents;" ::: "memory");
}

// ---------------------------------------------------------------------------
// Main kernel (PDL secondary): cvt-independent prologue first, then
// griddepcontrol.wait before gathering from g_ft16.
// ---------------------------------------------------------------------------
__global__ __launch_bounds__(NT, 2)
void nnue_kernel(const int* __restrict__ wi,
                 const int* __restrict__ bi,
                 const float4* __restrict__ fc1w,   // [32][128] float4
                 const float* __restrict__ fc1b,
                 const float4* __restrict__ fc2w,   // [32][8] float4
                 const float* __restrict__ fc2b,
                 const float* __restrict__ fc3w,
                 const float* __restrict__ fc3b,
                 float* __restrict__ out)
{
    __shared__ __align__(16) int     s_idx[P][2][BAGP];
    __shared__ __align__(16) __half2 s_xh[P][256];   // concat x, fp16
    __shared__ float s_h1[P][32];

    const int tid  = threadIdx.x;
    const int lane = tid & 31;
    const int warp = tid >> 5;
    const int p0   = blockIdx.x * P;

    // ---- prologue (independent of cvt): stage indices ----
    // zero the 2 pad slots of each (pos, tbl) row
    if (tid < P * 2 * 2) {
        const int slot = tid >> 1;          // (pp*2+tbl)
        const int j    = BAG + (tid & 1);   // 30 or 31
        s_idx[0][0][slot * BAGP + j] = 0;   // flat indexing
    }
    // fill the 480 real indices (contiguous per table)
    for (int i = tid; i < P * 2 * BAG; i += NT) {
        const int tbl = (i >= P * BAG);
        const int r   = tbl ? (i - P * BAG) : i;    // 0..239
        const int pp  = r / BAG;
        const int j   = r % BAG;
        const int v   = tbl ? bi[p0 * BAG + r] : wi[p0 * BAG + r];
        s_idx[pp][tbl][j] = v;
    }

    // ---- prologue: FC1 weights -> 64 registers ----
    uint64_t wp[4][8];
    float    b1r[4];
#pragma unroll
    for (int oo = 0; oo < 4; oo++) {
        const int o = 4 * warp + oo;
#pragma unroll
        for (int k = 0; k < 4; k++) {
            const float4 w = __ldg(&fc1w[(size_t)o * 128 + lane + 32 * k]);
            wp[oo][2 * k]     = pack_f32x2(w.x, w.y);
            wp[oo][2 * k + 1] = pack_f32x2(w.z, w.w);
        }
        b1r[oo] = __ldg(&fc1b[o]);
    }

    // ---- wait for cvt grid (PDL), then sync the block ----
    asm volatile("griddepcontrol.wait;" ::: "memory");
    __syncthreads();

    // ---- gather: warp w owns position w. 8 chunks x 4 rows per table. ----
    {
        uint64_t accW[4], accB[4];
#pragma unroll
        for (int k = 0; k < 4; k++) { accW[k] = 0ull; accB[k] = 0ull; }

        const uint4* tw = g_ft16[0];
        const uint4* tb = g_ft16[1];
        const int4* iw4 = reinterpret_cast<const int4*>(s_idx[warp][0]);
        const int4* ib4 = reinterpret_cast<const int4*>(s_idx[warp][1]);

#pragma unroll
        for (int c = 0; c < 8; c++) {      // 8 chunks x 4 rows
            const int4 iw = iw4[c];
            const int4 ib = ib4[c];

            uint4 vw0 = __ldcg(&tw[(size_t)iw.x * ROW_U4 + lane]);
            uint4 vw1 = __ldcg(&tw[(size_t)iw.y * ROW_U4 + lane]);
            uint4 vw2 = __ldcg(&tw[(size_t)iw.z * ROW_U4 + lane]);
            uint4 vw3 = __ldcg(&tw[(size_t)iw.w * ROW_U4 + lane]);
            uint4 vb0 = __ldcg(&tb[(size_t)ib.x * ROW_U4 + lane]);
            uint4 vb1 = __ldcg(&tb[(size_t)ib.y * ROW_U4 + lane]);
            uint4 vb2 = __ldcg(&tb[(size_t)ib.z * ROW_U4 + lane]);
            uint4 vb3 = __ldcg(&tb[(size_t)ib.w * ROW_U4 + lane]);

            const __half2* w0 = reinterpret_cast<const __half2*>(&vw0);
            const __half2* w1 = reinterpret_cast<const __half2*>(&vw1);
            const __half2* w2 = reinterpret_cast<const __half2*>(&vw2);
            const __half2* w3 = reinterpret_cast<const __half2*>(&vw3);
            const __half2* b0 = reinterpret_cast<const __half2*>(&vb0);
            const __half2* b1 = reinterpret_cast<const __half2*>(&vb1);
            const __half2* b2 = reinterpret_cast<const __half2*>(&vb2);
            const __half2* b3 = reinterpret_cast<const __half2*>(&vb3);

#pragma unroll
            for (int k = 0; k < 4; k++) {
                __half2 hw = __hadd2(__hadd2(w0[k], w1[k]),
                                     __hadd2(w2[k], w3[k]));
                __half2 hb = __hadd2(__hadd2(b0[k], b1[k]),
                                     __hadd2(b2[k], b3[k]));
                add_f32x2(accW[k], h2_to_f32x2(hw));
                add_f32x2(accB[k], h2_to_f32x2(hb));
            }
        }

        // relu in f32, convert to fp16, store: 2 x STS.128 per warp.
        __half2 hW[4], hB[4];
#pragma unroll
        for (int k = 0; k < 4; k++) {
            float2 fw = unpack_f32x2(accW[k]);
            float2 fb = unpack_f32x2(accB[k]);
            hW[k] = __floats2half2_rn(fmaxf(fw.x, 0.f), fmaxf(fw.y, 0.f));
            hB[k] = __floats2half2_rn(fmaxf(fb.x, 0.f), fmaxf(fb.y, 0.f));
        }
        *reinterpret_cast<uint4*>(&s_xh[warp][4 * lane]) =
            *reinterpret_cast<uint4*>(hW);          // white cols 8l..8l+7
        *reinterpret_cast<uint4*>(&s_xh[warp][128 + 4 * lane]) =
            *reinterpret_cast<uint4*>(hB);          // black
    }
    __syncthreads();

    // ---- FC1: warp computes its 4 outputs for all 8 positions ----
#pragma unroll
    for (int pos = 0; pos < P; pos++) {
        uint64_t xp[8];
#pragma unroll
        for (int k = 0; k < 4; k++) {
            const uint2 v = *reinterpret_cast<const uint2*>(
                &s_xh[pos][2 * (lane + 32 * k)]);
            const __half2 lo = *reinterpret_cast<const __half2*>(&v.x);
            const __half2 hi = *reinterpret_cast<const __half2*>(&v.y);
            xp[2 * k]     = h2_to_f32x2(lo);
            xp[2 * k + 1] = h2_to_f32x2(hi);
        }
        float part[4];
#pragma unroll
        for (int oo = 0; oo < 4; oo++) {
            uint64_t acc = 0ull;
#pragma unroll
            for (int k = 0; k < 8; k++)
                fma_f32x2(acc, wp[oo][k], xp[k]);
            const float2 f = unpack_f32x2(acc);
            part[oo] = f.x + f.y;
        }
#pragma unroll
        for (int off = 16; off > 0; off >>= 1) {
#pragma unroll
            for (int oo = 0; oo < 4; oo++)
                part[oo] += __shfl_xor_sync(0xffffffffu, part[oo], off);
        }
        if (lane == 0) {
#pragma unroll
            for (int oo = 0; oo < 4; oo++)
                s_h1[pos][4 * warp + oo] = fmaxf(part[oo] + b1r[oo], 0.f);
        }
    }
    __syncthreads();

    // ---- FC2 (32->32, relu) + FC3 (32->1): warp w handles position w ----
    {
        const float* h = s_h1[warp];
        float s = __ldg(&fc2b[lane]);
        const float4* w2 = fc2w + (size_t)lane * 8;
#pragma unroll
        for (int k = 0; k < 8; k++) {
            const float4 w = __ldg(&w2[k]);
            s += w.x * h[4 * k + 0];
            s += w.y * h[4 * k + 1];
            s += w.z * h[4 * k + 2];
            s += w.w * h[4 * k + 3];
        }
        float v = fmaxf(s, 0.f) * __ldg(&fc3w[lane]);
#pragma unroll
        for (int off = 16; off > 0; off >>= 1)
            v += __shfl_xor_sync(0xffffffffu, v, off);
        if (lane == 0)
            out[p0 + warp] = v + __ldg(&fc3b[0]);
    }
}

extern "C" void kernel_launch(void* const* d_in, const int* in_sizes, int n_in,
                              void* d_out, int out_size)
{
    const int*    wiP   = (const int*)d_in[0];
    const int*    biP   = (const int*)d_in[2];
    const float4* ftw   = (const float4*)d_in[4];
    const float4* ftb   = (const float4*)d_in[5];
    const float4* fc1w  = (const float4*)d_in[6];
    const float*  fc1b  = (const float*)d_in[7];
    const float4* fc2w  = (const float4*)d_in[8];
    const float*  fc2b  = (const float*)d_in[9];
    const float*  fc3w  = (const float*)d_in[10];
    const float*  fc3b  = (const float*)d_in[11];
    float* outP = (float*)d_out;

    const int n_cvt = 2 * TBL_U4;
    cvt_kernel<<<(n_cvt + 255) / 256, 256>>>(ftw, ftb);

    // PDL launch of the main kernel: may begin scheduling while cvt drains;
    // the kernel itself gates on griddepcontrol.wait before reading g_ft16.
    cudaLaunchConfig_t cfg = {};
    cfg.gridDim       = dim3(GRID);
    cfg.blockDim      = dim3(NT);
    cfg.dynamicSmemBytes = 0;
    cfg.stream        = 0;
    cudaLaunchAttribute attrs[1];
    attrs[0].id = cudaLaunchAttributeProgrammaticStreamSerialization;
    attrs[0].val.programmaticStreamSerializationAllowed = 1;
    cfg.attrs    = attrs;
    cfg.numAttrs = 1;
    cudaLaunchKernelEx(&cfg, nnue_kernel, wiP, biP, fc1w, fc1b,
                       fc2w, fc2b, fc3w, fc3b, outP);
}

// round 15
// speedup vs baseline: 1.1566x; 1.0114x over previous
#include <cuda_runtime.h>
#include <cuda_fp16.h>
#include <cstdint>

#define NUM_EMB 41025
#define BATCH   16384
#define BAG     30
#define BAGP    32         // padded bag (pad index = 0 -> zero row)
#define P       8          // positions per block (1 warp each)
#define NT      256
#define GRID    (BATCH / P)

#define ROW_U4  32                     // 256 halves = 32 uint4 per row
#define TBL_U4  (NUM_EMB * ROW_U4)     // 1,312,800 uint4 per table

// fp16 shadow tables (scratch): [0]=white, [1]=black. 21 MB each.
__device__ uint4 g_ft16[2][TBL_U4];

// ---- packed f32x2 helpers (Blackwell sm_103a) ----
__device__ __forceinline__ void add_f32x2(uint64_t& acc, uint64_t v) {
    asm("add.rn.f32x2 %0, %1, %2;" : "=l"(acc) : "l"(acc), "l"(v));
}
__device__ __forceinline__ void fma_f32x2(uint64_t& acc, uint64_t a, uint64_t b) {
    asm("fma.rn.f32x2 %0, %1, %2, %3;" : "=l"(acc) : "l"(a), "l"(b), "l"(acc));
}
__device__ __forceinline__ uint64_t h2_to_f32x2(__half2 h) {
    float2 f = __half22float2(h);
    uint64_t r;
    asm("mov.b64 %0, {%1, %2};" : "=l"(r) : "f"(f.x), "f"(f.y));
    return r;
}
__device__ __forceinline__ float2 unpack_f32x2(uint64_t v) {
    float2 f;
    asm("mov.b64 {%0, %1}, %2;" : "=f"(f.x), "=f"(f.y) : "l"(v));
    return f;
}
__device__ __forceinline__ uint64_t pack_f32x2(float x, float y) {
    uint64_t r;
    asm("mov.b64 %0, {%1, %2};" : "=l"(r) : "f"(x), "f"(y));
    return r;
}

// ---------------------------------------------------------------------------
// Pre-pass: convert both f32 tables to fp16 (streaming reads, L2 writes).
// ---------------------------------------------------------------------------
__global__ __launch_bounds__(256)
void cvt_kernel(const float4* __restrict__ ftw, const float4* __restrict__ ftb)
{
    const int i = blockIdx.x * blockDim.x + threadIdx.x;
    if (i >= 2 * TBL_U4) return;
    const int tbl = (i >= TBL_U4);
    const int j   = tbl ? (i - TBL_U4) : i;
    const float4* src = tbl ? ftb : ftw;

    const float4 a = __ldcs(&src[2 * j]);
    const float4 b = __ldcs(&src[2 * j + 1]);

    __half2 h0 = __floats2half2_rn(a.x, a.y);
    __half2 h1 = __floats2half2_rn(a.z, a.w);
    __half2 h2 = __floats2half2_rn(b.x, b.y);
    __half2 h3 = __floats2half2_rn(b.z, b.w);

    uint4 o;
    o.x = *reinterpret_cast<unsigned*>(&h0);
    o.y = *reinterpret_cast<unsigned*>(&h1);
    o.z = *reinterpret_cast<unsigned*>(&h2);
    o.w = *reinterpret_cast<unsigned*>(&h3);
    __stcg(&g_ft16[tbl][j], o);
}

// ---------------------------------------------------------------------------
// Main kernel. Explicit register double-buffered gather.
// ---------------------------------------------------------------------------
__global__ __launch_bounds__(NT, 2)
void nnue_kernel(const int* __restrict__ wi,
                 const int* __restrict__ bi,
                 const float4* __restrict__ fc1w,   // [32][128] float4
                 const float* __restrict__ fc1b,
                 const float4* __restrict__ fc2w,   // [32][8] float4
                 const float* __restrict__ fc2b,
                 const float* __restrict__ fc3w,
                 const float* __restrict__ fc3b,
                 float* __restrict__ out)
{
    __shared__ __align__(16) int     s_idx[P][2][BAGP];
    __shared__ __align__(16) __half2 s_xh[P][256];   // concat x, fp16
    __shared__ float s_h1[P][32];

    const int tid  = threadIdx.x;
    const int lane = tid & 31;
    const int warp = tid >> 5;
    const int p0   = blockIdx.x * P;

    // ---- per-warp index staging (no block barrier, no div/mod) ----
    {
        const int pos = p0 + warp;
        int vw = 0, vb = 0;
        if (lane < BAG) {
            vw = __ldg(&wi[pos * BAG + lane]);
            vb = __ldg(&bi[pos * BAG + lane]);
        }
        s_idx[warp][0][lane] = vw;      // lanes 30,31 write pad 0
        s_idx[warp][1][lane] = vb;
        __syncwarp();
    }

    // ---- gather: warp w owns position w. Register double-buffered:
    //      8 chunks x (4 white + 4 black) rows; two chunk buffers in flight.
    {
        uint64_t accW[4], accB[4];
#pragma unroll
        for (int k = 0; k < 4; k++) { accW[k] = 0ull; accB[k] = 0ull; }

        const uint4* tw = g_ft16[0];
        const uint4* tb = g_ft16[1];
        const int4* iw4 = reinterpret_cast<const int4*>(s_idx[warp][0]);
        const int4* ib4 = reinterpret_cast<const int4*>(s_idx[warp][1]);

        uint4 A[8], B[8];

        auto load_chunk = [&](uint4* buf, int c) {
            const int4 iw = iw4[c];
            const int4 ib = ib4[c];
            buf[0] = __ldcg(&tw[(size_t)iw.x * ROW_U4 + lane]);
            buf[1] = __ldcg(&tw[(size_t)iw.y * ROW_U4 + lane]);
            buf[2] = __ldcg(&tw[(size_t)iw.z * ROW_U4 + lane]);
            buf[3] = __ldcg(&tw[(size_t)iw.w * ROW_U4 + lane]);
            buf[4] = __ldcg(&tb[(size_t)ib.x * ROW_U4 + lane]);
            buf[5] = __ldcg(&tb[(size_t)ib.y * ROW_U4 + lane]);
            buf[6] = __ldcg(&tb[(size_t)ib.z * ROW_U4 + lane]);
            buf[7] = __ldcg(&tb[(size_t)ib.w * ROW_U4 + lane]);
        };

        auto consume = [&](const uint4* buf) {
            const __half2* r0 = reinterpret_cast<const __half2*>(&buf[0]);
            const __half2* r1 = reinterpret_cast<const __half2*>(&buf[1]);
            const __half2* r2 = reinterpret_cast<const __half2*>(&buf[2]);
            const __half2* r3 = reinterpret_cast<const __half2*>(&buf[3]);
            const __half2* r4 = reinterpret_cast<const __half2*>(&buf[4]);
            const __half2* r5 = reinterpret_cast<const __half2*>(&buf[5]);
            const __half2* r6 = reinterpret_cast<const __half2*>(&buf[6]);
            const __half2* r7 = reinterpret_cast<const __half2*>(&buf[7]);
#pragma unroll
            for (int k = 0; k < 4; k++) {
                __half2 hw = __hadd2(__hadd2(r0[k], r1[k]),
                                     __hadd2(r2[k], r3[k]));
                __half2 hb = __hadd2(__hadd2(r4[k], r5[k]),
                                     __hadd2(r6[k], r7[k]));
                add_f32x2(accW[k], h2_to_f32x2(hw));
                add_f32x2(accB[k], h2_to_f32x2(hb));
            }
        };

        load_chunk(A, 0);
        load_chunk(B, 1);
        consume(A); load_chunk(A, 2);
        consume(B); load_chunk(B, 3);
        consume(A); load_chunk(A, 4);
        consume(B); load_chunk(B, 5);
        consume(A); load_chunk(A, 6);
        consume(B); load_chunk(B, 7);
        consume(A);
        consume(B);

        // relu in f32, convert to fp16, store: 2 x STS.128 per warp.
        __half2 hW[4], hB[4];
#pragma unroll
        for (int k = 0; k < 4; k++) {
            float2 fw = unpack_f32x2(accW[k]);
            float2 fb = unpack_f32x2(accB[k]);
            hW[k] = __floats2half2_rn(fmaxf(fw.x, 0.f), fmaxf(fw.y, 0.f));
            hB[k] = __floats2half2_rn(fmaxf(fb.x, 0.f), fmaxf(fb.y, 0.f));
        }
        *reinterpret_cast<uint4*>(&s_xh[warp][4 * lane]) =
            *reinterpret_cast<uint4*>(hW);          // white cols 8l..8l+7
        *reinterpret_cast<uint4*>(&s_xh[warp][128 + 4 * lane]) =
            *reinterpret_cast<uint4*>(hB);          // black
    }

    // ---- FC1 weights -> 64 registers (after gather; A/B regs are dead) ----
    uint64_t wp[4][8];
    float    b1r[4];
#pragma unroll
    for (int oo = 0; oo < 4; oo++) {
        const int o = 4 * warp + oo;
#pragma unroll
        for (int k = 0; k < 4; k++) {
            const float4 w = __ldg(&fc1w[(size_t)o * 128 + lane + 32 * k]);
            wp[oo][2 * k]     = pack_f32x2(w.x, w.y);
            wp[oo][2 * k + 1] = pack_f32x2(w.z, w.w);
        }
        b1r[oo] = __ldg(&fc1b[o]);
    }
    __syncthreads();

    // ---- FC1: warp computes its 4 outputs for all 8 positions ----
#pragma unroll
    for (int pos = 0; pos < P; pos++) {
        uint64_t xp[8];
#pragma unroll
        for (int k = 0; k < 4; k++) {
            const uint2 v = *reinterpret_cast<const uint2*>(
                &s_xh[pos][2 * (lane + 32 * k)]);
            const __half2 lo = *reinterpret_cast<const __half2*>(&v.x);
            const __half2 hi = *reinterpret_cast<const __half2*>(&v.y);
            xp[2 * k]     = h2_to_f32x2(lo);
            xp[2 * k + 1] = h2_to_f32x2(hi);
        }
        float part[4];
#pragma unroll
        for (int oo = 0; oo < 4; oo++) {
            uint64_t acc = 0ull;
#pragma unroll
            for (int k = 0; k < 8; k++)
                fma_f32x2(acc, wp[oo][k], xp[k]);
            const float2 f = unpack_f32x2(acc);
            part[oo] = f.x + f.y;
        }
#pragma unroll
        for (int off = 16; off > 0; off >>= 1) {
#pragma unroll
            for (int oo = 0; oo < 4; oo++)
                part[oo] += __shfl_xor_sync(0xffffffffu, part[oo], off);
        }
        if (lane == 0) {
#pragma unroll
            for (int oo = 0; oo < 4; oo++)
                s_h1[pos][4 * warp + oo] = fmaxf(part[oo] + b1r[oo], 0.f);
        }
    }
    __syncthreads();

    // ---- FC2 (32->32, relu) + FC3 (32->1): warp w handles position w ----
    {
        const float* h = s_h1[warp];
        float s = __ldg(&fc2b[lane]);
        const float4* w2 = fc2w + (size_t)lane * 8;
#pragma unroll
        for (int k = 0; k < 8; k++) {
            const float4 w = __ldg(&w2[k]);
            s += w.x * h[4 * k + 0];
            s += w.y * h[4 * k + 1];
            s += w.z * h[4 * k + 2];
            s += w.w * h[4 * k + 3];
        }
        float v = fmaxf(s, 0.f) * __ldg(&fc3w[lane]);
#pragma unroll
        for (int off = 16; off > 0; off >>= 1)
            v += __shfl_xor_sync(0xffffffffu, v, off);
        if (lane == 0)
            out[p0 + warp] = v + __ldg(&fc3b[0]);
    }
}

extern "C" void kernel_launch(void* const* d_in, const int* in_sizes, int n_in,
                              void* d_out, int out_size)
{
    const int*    wiP   = (const int*)d_in[0];
    const int*    biP   = (const int*)d_in[2];
    const float4* ftw   = (const float4*)d_in[4];
    const float4* ftb   = (const float4*)d_in[5];
    const float4* fc1w  = (const float4*)d_in[6];
    const float*  fc1b  = (const float*)d_in[7];
    const float4* fc2w  = (const float4*)d_in[8];
    const float*  fc2b  = (const float*)d_in[9];
    const float*  fc3w  = (const float*)d_in[10];
    const float*  fc3b  = (const float*)d_in[11];
    float* outP = (float*)d_out;

    const int n_cvt = 2 * TBL_U4;
    cvt_kernel<<<(n_cvt + 255) / 256, 256>>>(ftw, ftb);
    nnue_kernel<<<GRID, NT>>>(wiP, biP, fc1w, fc1b,
                              fc2w, fc2b, fc3w, fc3b, outP);
}